// round 14
// baseline (speedup 1.0000x reference)
#include <cuda_runtime.h>

#define HH 256
#define WW 256
#define HW 65536
#define BS 8
#define IC 16
#define OC 32
#define NSTEPS 7
#define PXT 4   // pixels per thread in step kernel

typedef unsigned long long u64;

// Scratch (static device globals — no runtime allocation).
__device__ __align__(16) float2 g_raw[BS * IC * HW];   // conv output, interleaved (dy,dx) pre-BN
__device__ __align__(16) float2 g_fA[BS * IC * HW];    // interleaved flow ping
__device__ __align__(16) float2 g_fB[BS * IC * HW];    // interleaved flow pong
__device__ float g_part[2][OC][2048];                  // per-block partial (sum, sumsq)
__device__ float g_affa[OC];                           // BN affine scale (incl. 1/128)
__device__ float g_affb[OC];                           // BN affine shift (incl. 1/128)

__device__ __forceinline__ u64 pack2(float lo, float hi) {
    u64 r; asm("mov.b64 %0, {%1, %2};" : "=l"(r) : "f"(lo), "f"(hi)); return r;
}
__device__ __forceinline__ void unpack2(u64 v, float& lo, float& hi) {
    asm("mov.b64 {%0, %1}, %2;" : "=f"(lo), "=f"(hi) : "l"(v));
}
__device__ __forceinline__ u64 ffma2(u64 a, u64 b, u64 c) {
    u64 d; asm("fma.rn.f32x2 %0, %1, %2, %3;" : "=l"(d) : "l"(a), "l"(b), "l"(c)); return d;
}

// ---------------------------------------------------------------------------
// Conv 3x3 (16->32, pad 1) via packed f32x2 FMA + deterministic stats.
// Weights pre-duplicated in smem as u64 ([ic][kx][ky][oc] layout, broadcast
// LDS.64) — no per-iteration weight packing. Output written as interleaved
// float2 flow (dy,dx) so step 0 gets the cheap vector gather path.
// ---------------------------------------------------------------------------
__global__ __launch_bounds__(256) void conv_kernel(const float* __restrict__ f,
                                                   const float* __restrict__ vw,
                                                   const float* __restrict__ vb) {
    __shared__ float ft[IC * 10 * 34];
    __shared__ u64 ws2[IC * 9 * OC];   // ((ic*3+kx)*3+ky)*32 + oc, duplicated pairs

    const int tid  = threadIdx.x;
    const int lane = tid & 31;
    const int wid  = tid >> 5;
    const int x0   = blockIdx.x * 32;
    const int y0   = blockIdx.y * 8;
    const int b    = blockIdx.z;

    for (int i = tid; i < IC * 9 * OC; i += 256) {
        int oc = i & 31;
        int rest = i >> 5;
        int ky = rest % 3;
        int rest2 = rest / 3;
        int kx = rest2 % 3;
        int ic = rest2 / 3;
        float w = vw[oc * 144 + ic * 9 + ky * 3 + kx];
        ws2[i] = pack2(w, w);
    }

    const float* fb = f + (size_t)b * IC * HW;
    for (int i = tid; i < IC * 10 * 34; i += 256) {
        int ic = i / 340;
        int rem = i % 340;
        int r = rem / 34, cc = rem % 34;
        int yy = y0 - 1 + r, xx = x0 - 1 + cc;
        float v = 0.f;
        if (yy >= 0 && yy < HH && xx >= 0 && xx < WW) v = fb[ic * HW + yy * WW + xx];
        ft[i] = v;
    }
    __syncthreads();

    const int oc0 = wid * 4;
    u64 acc[4][4];   // 4 oc x 4 pixel-pairs (8 rows)
#pragma unroll
    for (int i = 0; i < 4; i++) {
        float bias = vb[oc0 + i];
        u64 bp = pack2(bias, bias);
#pragma unroll
        for (int j = 0; j < 4; j++) acc[i][j] = bp;
    }

    for (int ic = 0; ic < IC; ic++) {
        const float* ftc = ft + ic * 340;
#pragma unroll
        for (int kx = 0; kx < 3; kx++) {
            float col[10];
#pragma unroll
            for (int r = 0; r < 10; r++) col[r] = ftc[r * 34 + lane + kx];
            u64 colp[9];
#pragma unroll
            for (int r = 0; r < 9; r++) colp[r] = pack2(col[r], col[r + 1]);
            const u64* wrow = ws2 + (size_t)((ic * 3 + kx) * 3) * 32;
#pragma unroll
            for (int i = 0; i < 4; i++) {
#pragma unroll
                for (int ky = 0; ky < 3; ky++) {
                    u64 wd = wrow[ky * 32 + oc0 + i];
#pragma unroll
                    for (int j = 0; j < 4; j++)
                        acc[i][j] = ffma2(colp[2 * j + ky], wd, acc[i][j]);
                }
            }
        }
    }

    // Unpack, per-oc stats, interleaved float2 stores.
    float vals[4][8];
#pragma unroll
    for (int i = 0; i < 4; i++)
#pragma unroll
        for (int jp = 0; jp < 4; jp++)
            unpack2(acc[i][jp], vals[i][2 * jp], vals[i][2 * jp + 1]);

    const int blk = (b * (int)gridDim.y + blockIdx.y) * (int)gridDim.x + blockIdx.x;
#pragma unroll
    for (int i = 0; i < 4; i++) {
        float s = 0.f, s2 = 0.f;
#pragma unroll
        for (int r = 0; r < 8; r++) {
            float v = vals[i][r];
            s += v;
            s2 += v * v;
        }
#pragma unroll
        for (int off = 16; off > 0; off >>= 1) {
            s  += __shfl_down_sync(0xffffffffu, s, off);
            s2 += __shfl_down_sync(0xffffffffu, s2, off);
        }
        if (lane == 0) {
            g_part[0][oc0 + i][blk] = s;
            g_part[1][oc0 + i][blk] = s2;
        }
    }

    // flow channels wid*2 + {0,1}: (dy,dx) = (vals[2*i2], vals[2*i2+1])
#pragma unroll
    for (int i2 = 0; i2 < 2; i2++) {
        float2* dst = g_raw + (size_t)(b * IC + wid * 2 + i2) * HW + y0 * WW + x0 + lane;
#pragma unroll
        for (int r = 0; r < 8; r++) {
            float2 v; v.x = vals[2 * i2][r]; v.y = vals[2 * i2 + 1][r];
            dst[r * WW] = v;
        }
    }
}

// ---------------------------------------------------------------------------
// Reduce partials -> BN affine, folded with 1/2^NSTEPS.
// ---------------------------------------------------------------------------
__global__ __launch_bounds__(256) void stats_kernel(const float* __restrict__ gamma,
                                                    const float* __restrict__ beta) {
    __shared__ float sm[256], sm2[256];
    const int ch = blockIdx.x, tid = threadIdx.x;
    float s = 0.f, s2 = 0.f;
    for (int i = tid; i < 2048; i += 256) {
        s += g_part[0][ch][i];
        s2 += g_part[1][ch][i];
    }
    sm[tid] = s; sm2[tid] = s2;
    __syncthreads();
    for (int off = 128; off > 0; off >>= 1) {
        if (tid < off) { sm[tid] += sm[tid + off]; sm2[tid] += sm2[tid + off]; }
        __syncthreads();
    }
    if (tid == 0) {
        const float n = (float)(BS * HW);
        float mean = sm[0] / n;
        float var = sm2[0] / n - mean * mean;
        float r = rsqrtf(var + 1e-5f);
        const float scale = 1.0f / 128.0f;
        g_affa[ch] = gamma[ch] * r * scale;
        g_affb[ch] = (beta[ch] - gamma[ch] * mean * r) * scale;
    }
}

// ---------------------------------------------------------------------------
// One fused scaling-and-squaring step.
// Block = 512 threads, tile = 32*PXT consecutive pixels; PXT pixels/thread,
// staged so the PXT dependent-load chains interleave (MLP = PXT).
// All steps (incl. FIRST) read interleaved float2 flow; FIRST additionally
// applies the BN affine to center and every valid tap (identical arithmetic
// to the reference: invalid taps contribute exactly 0).
// LAST skips the never-read flow store.
// ---------------------------------------------------------------------------
template <bool FIRST, bool LAST>
__global__ __launch_bounds__(512, 2) void step_kernel(const float* __restrict__ f,
                                                      const float* __restrict__ fw,
                                                      const float* __restrict__ fbias,
                                                      float* __restrict__ out,
                                                      int step) {
    __shared__ float ws[256];                // [o][c]
    __shared__ float fb_s[16];
    __shared__ float sm_m[16][32 * PXT + 1]; // [c][px] padded

    const int tid = threadIdx.x;
    if (tid < 256) {
        int o = tid >> 4, c = tid & 15;
        ws[o * 16 + c] = fw[(o * 16 + c) * NSTEPS + step];
    }
    if (tid < 16) fb_s[tid] = fbias[tid];

    const int pix0 = blockIdx.x * (32 * PXT);
    const int b  = pix0 >> 16;
    const int p0 = pix0 & 65535;
    const int cc = tid >> 5;
    const int pj = tid & 31;

    // ---------------- phase 1: PXT pixels per (channel) thread --------------
    {
        const int c = cc;
        const float2* pc = (FIRST ? g_raw : ((step & 1) ? g_fA : g_fB))
                         + (size_t)(b * IC + c) * HW;
        float a0 = 1.f, b0 = 0.f, a1 = 1.f, b1 = 0.f;
        if (FIRST) {
            a0 = g_affa[2 * c];     b0 = g_affb[2 * c];
            a1 = g_affa[2 * c + 1]; b1 = g_affb[2 * c + 1];
        }

        float dy[PXT], dx[PXT];

        // stage A: all center loads
#pragma unroll
        for (int j = 0; j < PXT; j++) {
            float2 cv = pc[p0 + pj + 32 * j];
            if (FIRST) {
                dy[j] = a0 * cv.x + b0;
                dx[j] = a1 * cv.y + b1;
            } else {
                dy[j] = cv.x; dx[j] = cv.y;
            }
        }

        // stage B: all tap rounds + integrate
        float ndy[PXT], ndx[PXT];
#pragma unroll
        for (int j = 0; j < PXT; j++) {
            int p = p0 + pj + 32 * j;
            float fy = (float)(p >> 8), fx = (float)(p & 255);
            float py = fy + dy[j], px = fx + dx[j];
            float yf = floorf(py), xf = floorf(px);
            float wy1 = py - yf, wy0 = 1.f - wy1;
            float wx1 = px - xf, wx0 = 1.f - wx1;
            int yi = (int)yf, xi = (int)xf;
            float wdy = 0.f, wdx = 0.f;
#pragma unroll
            for (int t = 0; t < 4; t++) {
                int ty = yi + (t >> 1), tx = xi + (t & 1);
                float wgt = ((t >> 1) ? wy1 : wy0) * ((t & 1) ? wx1 : wx0);
                if ((unsigned)ty < (unsigned)HH && (unsigned)tx < (unsigned)WW) {
                    float2 v = pc[ty * WW + tx];
                    if (FIRST) {
                        wdy += wgt * (a0 * v.x + b0);
                        wdx += wgt * (a1 * v.y + b1);
                    } else {
                        wdy += wgt * v.x;
                        wdx += wgt * v.y;
                    }
                }
            }
            ndy[j] = dy[j] + wdy;
            ndx[j] = dx[j] + wdx;
        }

        // stage C: all flow stores
        if (!LAST) {
            float2* vout = (FIRST ? g_fA : ((step & 1) ? g_fB : g_fA))
                         + (size_t)(b * IC + c) * HW;
#pragma unroll
            for (int j = 0; j < PXT; j++) {
                float2 sv; sv.x = ndy[j]; sv.y = ndx[j];
                vout[p0 + pj + 32 * j] = sv;
            }
        }

        // stage D: all f gathers -> smem
        const float* fp = f + (size_t)(b * IC + c) * HW;
#pragma unroll
        for (int j = 0; j < PXT; j++) {
            int p = p0 + pj + 32 * j;
            float fy = (float)(p >> 8), fx = (float)(p & 255);
            float qy = fy + ndy[j], qx = fx + ndx[j];
            float yf = floorf(qy), xf = floorf(qx);
            float vy1 = qy - yf, vy0 = 1.f - vy1;
            float vx1 = qx - xf, vx0 = 1.f - vx1;
            int yi = (int)yf, xi = (int)xf;
            float m = 0.f;
#pragma unroll
            for (int t = 0; t < 4; t++) {
                int ty = yi + (t >> 1), tx = xi + (t & 1);
                float wgt = ((t >> 1) ? vy1 : vy0) * ((t & 1) ? vx1 : vx0);
                if ((unsigned)ty < (unsigned)HH && (unsigned)tx < (unsigned)WW)
                    m += wgt * fp[ty * WW + tx];
            }
            sm_m[c][pj + 32 * j] = m;
        }
    }

    __syncthreads();

    // ---------------- phase 2: PXT pixels per (output) thread ---------------
    {
        const int o = cc;
        float* op = out + (size_t)(b * IC + o) * HW + p0 + pj;

        float acc[PXT];
#pragma unroll
        for (int j = 0; j < PXT; j++)
            acc[j] = FIRST ? fb_s[o] : op[32 * j];
#pragma unroll
        for (int c = 0; c < 16; c++) {
            float w = ws[o * 16 + c];
#pragma unroll
            for (int j = 0; j < PXT; j++)
                acc[j] += w * sm_m[c][pj + 32 * j];
        }
#pragma unroll
        for (int j = 0; j < PXT; j++)
            op[32 * j] = acc[j];
    }
}

extern "C" void kernel_launch(void* const* d_in, const int* in_sizes, int n_in,
                              void* d_out, int out_size) {
    const float* f     = (const float*)d_in[0];
    const float* vw    = (const float*)d_in[1];
    const float* vb    = (const float*)d_in[2];
    const float* gamma = (const float*)d_in[3];
    const float* beta  = (const float*)d_in[4];
    const float* fw    = (const float*)d_in[5];
    const float* fbias = (const float*)d_in[6];
    float* out = (float*)d_out;

    dim3 cg(8, 32, 8);
    conv_kernel<<<cg, 256>>>(f, vw, vb);
    stats_kernel<<<32, 256>>>(gamma, beta);
    const int nblk = BS * HW / (32 * PXT);   // 4096
    // step 0 reads g_raw -> writes g_fA; step s>=1: odd reads g_fA->writes g_fB, even reads g_fB->writes g_fA
    step_kernel<true, false><<<nblk, 512>>>(f, fw, fbias, out, 0);
    for (int s = 1; s < NSTEPS - 1; s++)
        step_kernel<false, false><<<nblk, 512>>>(f, fw, fbias, out, s);
    step_kernel<false, true><<<nblk, 512>>>(f, fw, fbias, out, NSTEPS - 1);
}

// round 17
// speedup vs baseline: 1.0668x; 1.0668x over previous
#include <cuda_runtime.h>

#define HH 256
#define WW 256
#define HW 65536
#define BS 8
#define IC 16
#define OC 32
#define NSTEPS 7
#define PXT 4   // pixels per thread in step kernel

typedef unsigned long long u64;

// Scratch (static device globals — no runtime allocation).
__device__ __align__(16) float2 g_raw[BS * IC * HW];   // conv output, interleaved (dy,dx) pre-BN
__device__ __align__(16) float2 g_fA[BS * IC * HW];    // interleaved flow ping
__device__ __align__(16) float2 g_fB[BS * IC * HW];    // interleaved flow pong
__device__ float g_part[2][OC][2048];                  // per-block partial (sum, sumsq)
__device__ float g_affa[OC];                           // BN affine scale (incl. 1/128)
__device__ float g_affb[OC];                           // BN affine shift (incl. 1/128)

__device__ __forceinline__ u64 pack2(float lo, float hi) {
    u64 r; asm("mov.b64 %0, {%1, %2};" : "=l"(r) : "f"(lo), "f"(hi)); return r;
}
__device__ __forceinline__ void unpack2(u64 v, float& lo, float& hi) {
    asm("mov.b64 {%0, %1}, %2;" : "=f"(lo), "=f"(hi) : "l"(v));
}
__device__ __forceinline__ u64 ffma2(u64 a, u64 b, u64 c) {
    u64 d; asm("fma.rn.f32x2 %0, %1, %2, %3;" : "=l"(d) : "l"(a), "l"(b), "l"(c)); return d;
}

// ---------------------------------------------------------------------------
// Conv 3x3 (16->32, pad 1) via packed f32x2 FMA + deterministic stats.
// R12 compute path (small float ws smem, pack2 at use — measured fastest);
// output stored as interleaved float2 flow (dy,dx) so step 0 gets the cheap
// vector gather path.
// ---------------------------------------------------------------------------
__global__ __launch_bounds__(256) void conv_kernel(const float* __restrict__ f,
                                                   const float* __restrict__ vw,
                                                   const float* __restrict__ vb) {
    __shared__ float ft[IC * 10 * 34];
    __shared__ float ws[OC * 144];

    const int tid  = threadIdx.x;
    const int lane = tid & 31;
    const int wid  = tid >> 5;
    const int x0   = blockIdx.x * 32;
    const int y0   = blockIdx.y * 8;
    const int b    = blockIdx.z;

    for (int i = tid; i < OC * 144; i += 256) ws[i] = vw[i];

    const float* fb = f + (size_t)b * IC * HW;
    for (int i = tid; i < IC * 10 * 34; i += 256) {
        int ic = i / 340;
        int rem = i % 340;
        int r = rem / 34, cc = rem % 34;
        int yy = y0 - 1 + r, xx = x0 - 1 + cc;
        float v = 0.f;
        if (yy >= 0 && yy < HH && xx >= 0 && xx < WW) v = fb[ic * HW + yy * WW + xx];
        ft[i] = v;
    }
    __syncthreads();

    const int oc0 = wid * 4;
    u64 acc[4][4];   // 4 oc x 4 pixel-pairs (8 rows)
#pragma unroll
    for (int i = 0; i < 4; i++) {
        float bias = vb[oc0 + i];
        u64 bp = pack2(bias, bias);
#pragma unroll
        for (int j = 0; j < 4; j++) acc[i][j] = bp;
    }

    for (int ic = 0; ic < IC; ic++) {
        const float* ftc = ft + ic * 340;
#pragma unroll
        for (int kx = 0; kx < 3; kx++) {
            float col[10];
#pragma unroll
            for (int r = 0; r < 10; r++) col[r] = ftc[r * 34 + lane + kx];
            u64 colp[9];
#pragma unroll
            for (int r = 0; r < 9; r++) colp[r] = pack2(col[r], col[r + 1]);
#pragma unroll
            for (int i = 0; i < 4; i++) {
#pragma unroll
                for (int ky = 0; ky < 3; ky++) {
                    float w = ws[(oc0 + i) * 144 + ic * 9 + ky * 3 + kx];
                    u64 wd = pack2(w, w);
#pragma unroll
                    for (int j = 0; j < 4; j++)
                        acc[i][j] = ffma2(colp[2 * j + ky], wd, acc[i][j]);
                }
            }
        }
    }

    // Unpack, per-oc stats, interleaved float2 stores.
    float vals[4][8];
#pragma unroll
    for (int i = 0; i < 4; i++)
#pragma unroll
        for (int jp = 0; jp < 4; jp++)
            unpack2(acc[i][jp], vals[i][2 * jp], vals[i][2 * jp + 1]);

    const int blk = (b * (int)gridDim.y + blockIdx.y) * (int)gridDim.x + blockIdx.x;
#pragma unroll
    for (int i = 0; i < 4; i++) {
        float s = 0.f, s2 = 0.f;
#pragma unroll
        for (int r = 0; r < 8; r++) {
            float v = vals[i][r];
            s += v;
            s2 += v * v;
        }
#pragma unroll
        for (int off = 16; off > 0; off >>= 1) {
            s  += __shfl_down_sync(0xffffffffu, s, off);
            s2 += __shfl_down_sync(0xffffffffu, s2, off);
        }
        if (lane == 0) {
            g_part[0][oc0 + i][blk] = s;
            g_part[1][oc0 + i][blk] = s2;
        }
    }

    // flow channels wid*2 + {0,1}: (dy,dx) = (vals[2*i2], vals[2*i2+1])
#pragma unroll
    for (int i2 = 0; i2 < 2; i2++) {
        float2* dst = g_raw + (size_t)(b * IC + wid * 2 + i2) * HW + y0 * WW + x0 + lane;
#pragma unroll
        for (int r = 0; r < 8; r++) {
            float2 v; v.x = vals[2 * i2][r]; v.y = vals[2 * i2 + 1][r];
            dst[r * WW] = v;
        }
    }
}

// ---------------------------------------------------------------------------
// Reduce partials -> BN affine, folded with 1/2^NSTEPS.
// ---------------------------------------------------------------------------
__global__ __launch_bounds__(256) void stats_kernel(const float* __restrict__ gamma,
                                                    const float* __restrict__ beta) {
    __shared__ float sm[256], sm2[256];
    const int ch = blockIdx.x, tid = threadIdx.x;
    float s = 0.f, s2 = 0.f;
    for (int i = tid; i < 2048; i += 256) {
        s += g_part[0][ch][i];
        s2 += g_part[1][ch][i];
    }
    sm[tid] = s; sm2[tid] = s2;
    __syncthreads();
    for (int off = 128; off > 0; off >>= 1) {
        if (tid < off) { sm[tid] += sm[tid + off]; sm2[tid] += sm2[tid + off]; }
        __syncthreads();
    }
    if (tid == 0) {
        const float n = (float)(BS * HW);
        float mean = sm[0] / n;
        float var = sm2[0] / n - mean * mean;
        float r = rsqrtf(var + 1e-5f);
        const float scale = 1.0f / 128.0f;
        g_affa[ch] = gamma[ch] * r * scale;
        g_affb[ch] = (beta[ch] - gamma[ch] * mean * r) * scale;
    }
}

// ---------------------------------------------------------------------------
// One fused scaling-and-squaring step.
// Block = 512 threads, tile = 32*PXT consecutive pixels; PXT pixels/thread,
// staged so the PXT dependent-load chains interleave (MLP = PXT).
// All steps (incl. FIRST) read interleaved float2 flow; FIRST additionally
// applies the BN affine to center and every valid tap.
// LAST skips the never-read flow store.
// ---------------------------------------------------------------------------
template <bool FIRST, bool LAST>
__global__ __launch_bounds__(512, 2) void step_kernel(const float* __restrict__ f,
                                                      const float* __restrict__ fw,
                                                      const float* __restrict__ fbias,
                                                      float* __restrict__ out,
                                                      int step) {
    __shared__ float ws[256];                // [o][c]
    __shared__ float fb_s[16];
    __shared__ float sm_m[16][32 * PXT + 1]; // [c][px] padded

    const int tid = threadIdx.x;
    if (tid < 256) {
        int o = tid >> 4, c = tid & 15;
        ws[o * 16 + c] = fw[(o * 16 + c) * NSTEPS + step];
    }
    if (tid < 16) fb_s[tid] = fbias[tid];

    const int pix0 = blockIdx.x * (32 * PXT);
    const int b  = pix0 >> 16;
    const int p0 = pix0 & 65535;
    const int cc = tid >> 5;
    const int pj = tid & 31;

    // ---------------- phase 1: PXT pixels per (channel) thread --------------
    {
        const int c = cc;
        const float2* pc = (FIRST ? g_raw : ((step & 1) ? g_fA : g_fB))
                         + (size_t)(b * IC + c) * HW;
        float a0 = 1.f, b0 = 0.f, a1 = 1.f, b1 = 0.f;
        if (FIRST) {
            a0 = g_affa[2 * c];     b0 = g_affb[2 * c];
            a1 = g_affa[2 * c + 1]; b1 = g_affb[2 * c + 1];
        }

        float dy[PXT], dx[PXT];

        // stage A: all center loads
#pragma unroll
        for (int j = 0; j < PXT; j++) {
            float2 cv = pc[p0 + pj + 32 * j];
            if (FIRST) {
                dy[j] = a0 * cv.x + b0;
                dx[j] = a1 * cv.y + b1;
            } else {
                dy[j] = cv.x; dx[j] = cv.y;
            }
        }

        // stage B: all tap rounds + integrate
        float ndy[PXT], ndx[PXT];
#pragma unroll
        for (int j = 0; j < PXT; j++) {
            int p = p0 + pj + 32 * j;
            float fy = (float)(p >> 8), fx = (float)(p & 255);
            float py = fy + dy[j], px = fx + dx[j];
            float yf = floorf(py), xf = floorf(px);
            float wy1 = py - yf, wy0 = 1.f - wy1;
            float wx1 = px - xf, wx0 = 1.f - wx1;
            int yi = (int)yf, xi = (int)xf;
            float wdy = 0.f, wdx = 0.f;
#pragma unroll
            for (int t = 0; t < 4; t++) {
                int ty = yi + (t >> 1), tx = xi + (t & 1);
                float wgt = ((t >> 1) ? wy1 : wy0) * ((t & 1) ? wx1 : wx0);
                if ((unsigned)ty < (unsigned)HH && (unsigned)tx < (unsigned)WW) {
                    float2 v = pc[ty * WW + tx];
                    if (FIRST) {
                        wdy += wgt * (a0 * v.x + b0);
                        wdx += wgt * (a1 * v.y + b1);
                    } else {
                        wdy += wgt * v.x;
                        wdx += wgt * v.y;
                    }
                }
            }
            ndy[j] = dy[j] + wdy;
            ndx[j] = dx[j] + wdx;
        }

        // stage C: all flow stores
        if (!LAST) {
            float2* vout = (FIRST ? g_fA : ((step & 1) ? g_fB : g_fA))
                         + (size_t)(b * IC + c) * HW;
#pragma unroll
            for (int j = 0; j < PXT; j++) {
                float2 sv; sv.x = ndy[j]; sv.y = ndx[j];
                vout[p0 + pj + 32 * j] = sv;
            }
        }

        // stage D: all f gathers -> smem
        const float* fp = f + (size_t)(b * IC + c) * HW;
#pragma unroll
        for (int j = 0; j < PXT; j++) {
            int p = p0 + pj + 32 * j;
            float fy = (float)(p >> 8), fx = (float)(p & 255);
            float qy = fy + ndy[j], qx = fx + ndx[j];
            float yf = floorf(qy), xf = floorf(qx);
            float vy1 = qy - yf, vy0 = 1.f - vy1;
            float vx1 = qx - xf, vx0 = 1.f - vx1;
            int yi = (int)yf, xi = (int)xf;
            float m = 0.f;
#pragma unroll
            for (int t = 0; t < 4; t++) {
                int ty = yi + (t >> 1), tx = xi + (t & 1);
                float wgt = ((t >> 1) ? vy1 : vy0) * ((t & 1) ? vx1 : vx0);
                if ((unsigned)ty < (unsigned)HH && (unsigned)tx < (unsigned)WW)
                    m += wgt * fp[ty * WW + tx];
            }
            sm_m[c][pj + 32 * j] = m;
        }
    }

    __syncthreads();

    // ---------------- phase 2: PXT pixels per (output) thread ---------------
    {
        const int o = cc;
        float* op = out + (size_t)(b * IC + o) * HW + p0 + pj;

        float acc[PXT];
#pragma unroll
        for (int j = 0; j < PXT; j++)
            acc[j] = FIRST ? fb_s[o] : op[32 * j];
#pragma unroll
        for (int c = 0; c < 16; c++) {
            float w = ws[o * 16 + c];
#pragma unroll
            for (int j = 0; j < PXT; j++)
                acc[j] += w * sm_m[c][pj + 32 * j];
        }
#pragma unroll
        for (int j = 0; j < PXT; j++)
            op[32 * j] = acc[j];
    }
}

extern "C" void kernel_launch(void* const* d_in, const int* in_sizes, int n_in,
                              void* d_out, int out_size) {
    const float* f     = (const float*)d_in[0];
    const float* vw    = (const float*)d_in[1];
    const float* vb    = (const float*)d_in[2];
    const float* gamma = (const float*)d_in[3];
    const float* beta  = (const float*)d_in[4];
    const float* fw    = (const float*)d_in[5];
    const float* fbias = (const float*)d_in[6];
    float* out = (float*)d_out;

    dim3 cg(8, 32, 8);
    conv_kernel<<<cg, 256>>>(f, vw, vb);
    stats_kernel<<<32, 256>>>(gamma, beta);
    const int nblk = BS * HW / (32 * PXT);   // 4096
    // step 0 reads g_raw -> writes g_fA; step s>=1: odd reads g_fA->writes g_fB, even reads g_fB->writes g_fA
    step_kernel<true, false><<<nblk, 512>>>(f, fw, fbias, out, 0);
    for (int s = 1; s < NSTEPS - 1; s++)
        step_kernel<false, false><<<nblk, 512>>>(f, fw, fbias, out, s);
    step_kernel<false, true><<<nblk, 512>>>(f, fw, fbias, out, NSTEPS - 1);
}